// round 10
// baseline (speedup 1.0000x reference)
#include <cuda_runtime.h>
#include <cuda_fp16.h>
#include <cstdint>
#include <cstddef>

// ---------------- problem dims (fixed by the dataset instance) ----------------
#define BLOCK   128
#define EMBED   4096
#define HIDDEN  16384
#define OUTD    4096
#define NZB     32
#define MACT    (NZB * BLOCK)   // 4096 active rows

// ---------------- scratch (device globals: allocation-free rule) -------------
__device__ __half d_g  [(size_t)MACT   * EMBED ];  // gathered activations fp16 [M,K]
__device__ __half d_w1t[(size_t)HIDDEN * EMBED ];  // fc1^T fp16 [N=HIDDEN, K=EMBED]
__device__ __half d_w2t[(size_t)OUTD   * HIDDEN];  // fc2^T fp16 [N=OUTD,   K=HIDDEN]
__device__ __half d_h  [(size_t)MACT   * HIDDEN];  // hidden fp16 [M,K2]

// ---------------- PTX helpers (all portable, sm_80-level) ---------------------
__device__ __forceinline__ uint32_t smem_u32(const void* p) {
    uint32_t a;
    asm("{ .reg .u64 t; cvta.to.shared.u64 t, %1; cvt.u32.u64 %0, t; }" : "=r"(a) : "l"(p));
    return a;
}
__device__ __forceinline__ void cp16(uint32_t dst, const void* src) {
    asm volatile("cp.async.cg.shared.global [%0], [%1], 16;" :: "r"(dst), "l"(src) : "memory");
}
#define CP_COMMIT()  asm volatile("cp.async.commit_group;" ::: "memory")
#define CP_WAIT1()   asm volatile("cp.async.wait_group 1;" ::: "memory")
#define SW128(o) ((o) ^ (((o) >> 3) & 0x70))

__device__ __forceinline__ void ldsm_x4(uint32_t* r, uint32_t addr) {
    asm volatile("ldmatrix.sync.aligned.m8n8.x4.shared.b16 {%0,%1,%2,%3}, [%4];"
                 : "=r"(r[0]), "=r"(r[1]), "=r"(r[2]), "=r"(r[3]) : "r"(addr));
}
__device__ __forceinline__ void mma16816(float* c, const uint32_t* a, const uint32_t* b) {
    asm volatile(
        "mma.sync.aligned.m16n8k16.row.col.f32.f16.f16.f32 "
        "{%0,%1,%2,%3}, {%4,%5,%6,%7}, {%8,%9}, {%0,%1,%2,%3};"
        : "+f"(c[0]), "+f"(c[1]), "+f"(c[2]), "+f"(c[3])
        : "r"(a[0]), "r"(a[1]), "r"(a[2]), "r"(a[3]), "r"(b[0]), "r"(b[1]));
}

// ---------------- conversion kernels -----------------------------------------
__global__ void gather_convert(const float* __restrict__ x, const int* __restrict__ nz,
                               __half* __restrict__ g) {
    size_t idx  = (size_t)blockIdx.x * blockDim.x + threadIdx.x;  // over MACT*EMBED/4
    int    row  = (int)(idx >> 10);            // EMBED/4 = 1024 float4 per row
    int    col4 = (int)(idx & 1023);
    int    blk  = row >> 7;
    int    srow = nz[blk] * BLOCK + (row & 127);
    float4 v = reinterpret_cast<const float4*>(x)[(size_t)srow * (EMBED / 4) + col4];
    __half2* dst = reinterpret_cast<__half2*>(g + (size_t)row * EMBED + (size_t)col4 * 4);
    dst[0] = __floats2half2_rn(v.x, v.y);
    dst[1] = __floats2half2_rn(v.z, v.w);
}

// in [R,C] fp32 row-major -> out [C,R] fp16 row-major
__global__ void transpose_convert(const float* __restrict__ in, __half* __restrict__ out,
                                  int R, int C) {
    __shared__ float tile[32][33];
    int c0 = blockIdx.x * 32, r0 = blockIdx.y * 32;
    int tx = threadIdx.x, ty = threadIdx.y;  // (32,8)
#pragma unroll
    for (int i = 0; i < 4; i++) {
        int y = ty + i * 8;
        tile[y][tx] = in[(size_t)(r0 + y) * C + c0 + tx];
    }
    __syncthreads();
#pragma unroll
    for (int i = 0; i < 4; i++) {
        int y = ty + i * 8;
        out[(size_t)(c0 + y) * R + r0 + tx] = __float2half(tile[tx][y]);
    }
}

// ---------------- HMMA GEMM ---------------------------------------------------
// C[m,n] = sum_k A[m,k]*B[n,k]; A:[M,KTOT] fp16 K-major, B:[Ntot,KTOT] fp16 K-major.
// Limiter analysis (R5-R9): smem crossbar (128B/cyc) was co-saturated with the
// tensor pipe at small warp tiles. Fix: 64x64 warp tiles -> 16 MACs per smem
// byte; CTA reads 64KB/iter = 512 cyc << 1024 tensor cyc.
// CTA 128x128, BK=64, 3-stage cp.async (96KB), 128 threads = 4 warps (2m x 2n),
// 2 CTAs/SM (launch_bounds(128,2): reg cap 256, need ~185 -> no spills).
constexpr int BM = 128, BN = 128, BK = 64, STAGES = 3;
constexpr uint32_t ABYTES      = BM * BK * 2;          // 16384
constexpr uint32_t STAGE_BYTES = 2 * ABYTES;           // 32768
constexpr uint32_t SMEM_DYN    = STAGES * STAGE_BYTES; // 98304

// A fragments: 4 m16-tiles (rows wm*64 + i*16), one ldsm_x4 each
__device__ __forceinline__ void load_frag_a(uint32_t (&a)[4][4], uint32_t sA,
                                            int wm, int lane, int ks) {
#pragma unroll
    for (int i = 0; i < 4; i++) {
        const uint32_t r  = (uint32_t)(wm * 64 + i * 16 + (lane & 15));
        const uint32_t cb = (uint32_t)(ks * 32 + ((lane >> 4) << 4));
        ldsm_x4(a[i], sA + SW128(r * 128 + cb));
    }
}
// B fragments: 8 n8-tiles packed as 4 ldsm_x4 (two n8-tiles per x4):
// lane group g=lane>>3: rows += (g>>1)*8, k-half = g&1.
// regs: bf[j] = {b0(tile 2j), b1(tile 2j), b0(tile 2j+1), b1(tile 2j+1)}
__device__ __forceinline__ void load_frag_b(uint32_t (&b)[4][4], uint32_t sB,
                                            int wn, int lane, int ks) {
#pragma unroll
    for (int j = 0; j < 4; j++) {
        const int g = lane >> 3;
        const uint32_t r  = (uint32_t)(wn * 64 + j * 16 + ((g >> 1) << 3) + (lane & 7));
        const uint32_t cb = (uint32_t)(ks * 32 + ((g & 1) << 4));
        ldsm_x4(b[j], sB + SW128(r * 128 + cb));
    }
}

template <int KTOT, int LDC, bool SCATTER>
__global__ void __launch_bounds__(128, 2)
gemm_f16(const __half* __restrict__ A, const __half* __restrict__ B,
         void* __restrict__ C, const int* __restrict__ nz) {
    extern __shared__ char smem[];
    const uint32_t sb = smem_u32(smem);
    const int tid  = threadIdx.x;
    const int lane = tid & 31, wid = tid >> 5;
    const int wm = wid >> 1, wn = wid & 1;             // 2 x 2 warp grid, 64x64 tiles
    const int m0 = blockIdx.x * BM, n0 = blockIdx.y * BN;   // m-fast grid
    constexpr int KIT = KTOT / BK;

    // cp.async: 256 combined rows (0-127 = A, 128-255 = B); each thread owns
    // two full 128B rows (tid and tid+128), 8 x 16B chunks per row.
    const char* gr0 = (tid < BM)
        ? (const char*)(A + (size_t)(m0 + tid) * KTOT)
        : (const char*)(B + (size_t)(n0 + tid - BM) * KTOT);
    const char* gr1 = (const char*)(B + (size_t)(n0 + tid) * KTOT);  // row tid+128 is always B
    const uint32_t swb0 = (uint32_t)(tid * 128);
    const uint32_t swb1 = (uint32_t)((tid + 128) * 128);

    float acc[4][8][4];
#pragma unroll
    for (int i = 0; i < 4; i++)
#pragma unroll
        for (int j = 0; j < 8; j++)
#pragma unroll
            for (int q = 0; q < 4; q++) acc[i][j][q] = 0.f;

    // prologue: fill stages 0..STAGES-2 (2 commits)
#pragma unroll
    for (int s = 0; s < STAGES - 1; s++) {
        const uint32_t st = sb + (uint32_t)s * STAGE_BYTES;
        const size_t ko = (size_t)s * (BK * 2);
#pragma unroll
        for (int ch = 0; ch < 8; ch++)
            cp16(st + SW128(swb0 + ch * 16), gr0 + ko + ch * 16);
#pragma unroll
        for (int ch = 0; ch < 8; ch++)
            cp16(st + SW128(swb1 + ch * 16), gr1 + ko + ch * 16);
        CP_COMMIT();
    }

    for (int it = 0; it < KIT; it++) {
        // groups committed: 2+it, <=1 pending after wait -> stage it resident
        CP_WAIT1();
        __syncthreads();

        // issue stage it+2 into slot (it+2)%3 (stage it-1's slot, consumed last iter)
        const int ls = it + STAGES - 1;
        if (ls < KIT) {
            const uint32_t st = sb + (uint32_t)(ls % STAGES) * STAGE_BYTES;
            const size_t ko = (size_t)ls * (BK * 2);
#pragma unroll
            for (int ch = 0; ch < 8; ch++)
                cp16(st + SW128(swb0 + ch * 16), gr0 + ko + ch * 16);
#pragma unroll
            for (int ch = 0; ch < 8; ch++)
                cp16(st + SW128(swb1 + ch * 16), gr1 + ko + ch * 16);
        }
        CP_COMMIT();

        const uint32_t sA  = sb + (uint32_t)(it % STAGES) * STAGE_BYTES;
        const uint32_t sBs = sA + ABYTES;

#pragma unroll
        for (int ks = 0; ks < 4; ks++) {
            uint32_t af[4][4], bf[4][4];
            load_frag_a(af, sA, wm, lane, ks);
            load_frag_b(bf, sBs, wn, lane, ks);
#pragma unroll
            for (int i = 0; i < 4; i++)
#pragma unroll
                for (int j = 0; j < 4; j++) {
                    mma16816(acc[i][2 * j],     af[i], &bf[j][0]);
                    mma16816(acc[i][2 * j + 1], af[i], &bf[j][2]);
                }
        }
    }

    // ---------------- epilogue ----------------
    // frag (i,jj): rows wm*64+i*16+lane/4 (+8), cols wn*64+jj*8+2*(lane%4)
    const int rbase = wm * 64 + (lane >> 2);
    const int cbase = n0 + wn * 64 + 2 * (lane & 3);
    if (!SCATTER) {
        __half* Ch = (__half*)C;
#pragma unroll
        for (int i = 0; i < 4; i++) {
#pragma unroll
            for (int jj = 0; jj < 8; jj++) {
                const int col = cbase + jj * 8;
                const size_t r0 = (size_t)(m0 + rbase + i * 16) * LDC + col;
                const size_t r1 = r0 + (size_t)8 * LDC;
                *reinterpret_cast<__half2*>(Ch + r0) =
                    __floats2half2_rn(acc[i][jj][0], acc[i][jj][1]);
                *reinterpret_cast<__half2*>(Ch + r1) =
                    __floats2half2_rn(acc[i][jj][2], acc[i][jj][3]);
            }
        }
    } else {
        float* Cf = (float*)C;
        const int orow = nz[blockIdx.x] * BLOCK;   // m-tile (blockIdx.x) == source block
#pragma unroll
        for (int i = 0; i < 4; i++) {
#pragma unroll
            for (int jj = 0; jj < 8; jj++) {
                const int col = cbase + jj * 8;
                const size_t r0 = (size_t)(orow + rbase + i * 16) * LDC + col;
                const size_t r1 = r0 + (size_t)8 * LDC;
                *reinterpret_cast<float2*>(Cf + r0) =
                    make_float2(acc[i][jj][0], acc[i][jj][1]);
                *reinterpret_cast<float2*>(Cf + r1) =
                    make_float2(acc[i][jj][2], acc[i][jj][3]);
            }
        }
    }
}

// ---------------- launch ------------------------------------------------------
extern "C" void kernel_launch(void* const* d_in, const int* in_sizes, int n_in,
                              void* d_out, int out_size) {
    const float* x   = (const float*)d_in[0];
    const float* fc1 = (const float*)d_in[1];
    const float* fc2 = (const float*)d_in[2];
    const int*   nz  = (const int*)d_in[3];
    (void)in_sizes; (void)n_in;

    void *pg, *pw1, *pw2, *ph;
    cudaGetSymbolAddress(&pg,  d_g);
    cudaGetSymbolAddress(&pw1, d_w1t);
    cudaGetSymbolAddress(&pw2, d_w2t);
    cudaGetSymbolAddress(&ph,  d_h);

    cudaFuncSetAttribute(gemm_f16<EMBED, HIDDEN, false>,
                         cudaFuncAttributeMaxDynamicSharedMemorySize, SMEM_DYN);
    cudaFuncSetAttribute(gemm_f16<HIDDEN, OUTD, true>,
                         cudaFuncAttributeMaxDynamicSharedMemorySize, SMEM_DYN);

    // zero full output (non-active blocks must be 0)
    cudaMemsetAsync(d_out, 0, (size_t)out_size * sizeof(float));

    // fp16 conversions
    gather_convert<<<(MACT * (EMBED / 4)) / 256, 256>>>(x, nz, (__half*)pg);
    transpose_convert<<<dim3(HIDDEN / 32, EMBED / 32), dim3(32, 8)>>>(fc1, (__half*)pw1, EMBED, HIDDEN);
    transpose_convert<<<dim3(OUTD / 32, HIDDEN / 32), dim3(32, 8)>>>(fc2, (__half*)pw2, HIDDEN, OUTD);

    // GEMM1: h = g @ fc1^T-layout   (M=4096, N=16384, K=4096), m-fast grid
    gemm_f16<EMBED, HIDDEN, false>
        <<<dim3(MACT / BM, HIDDEN / BN), 128, SMEM_DYN>>>(
            (const __half*)pg, (const __half*)pw1, ph, nz);

    // GEMM2: out[nz] = h @ fc2^T-layout   (M=4096, N=4096, K=16384), fp32 scatter
    gemm_f16<HIDDEN, OUTD, true>
        <<<dim3(MACT / BM, OUTD / BN), 128, SMEM_DYN>>>(
            (const __half*)ph, (const __half*)pw2, d_out, nz);
}

// round 11
// speedup vs baseline: 1.9651x; 1.9651x over previous
#include <cuda_runtime.h>
#include <cuda_fp16.h>
#include <cstdint>
#include <cstddef>

// ---------------- problem dims (fixed by the dataset instance) ----------------
#define BLOCK   128
#define EMBED   4096
#define HIDDEN  16384
#define OUTD    4096
#define NZB     32
#define MACT    (NZB * BLOCK)   // 4096 active rows

// ---------------- scratch (device globals: allocation-free rule) -------------
__device__ __half d_g  [(size_t)MACT   * EMBED ];  // gathered activations fp16 [M,K]
__device__ __half d_w1t[(size_t)HIDDEN * EMBED ];  // fc1^T fp16 [N=HIDDEN, K=EMBED]
__device__ __half d_w2t[(size_t)OUTD   * HIDDEN];  // fc2^T fp16 [N=OUTD,   K=HIDDEN]
__device__ __half d_h  [(size_t)MACT   * HIDDEN];  // hidden fp16 [M,K2]

// ---------------- PTX helpers (all portable, sm_80-level) ---------------------
__device__ __forceinline__ uint32_t smem_u32(const void* p) {
    uint32_t a;
    asm("{ .reg .u64 t; cvta.to.shared.u64 t, %1; cvt.u32.u64 %0, t; }" : "=r"(a) : "l"(p));
    return a;
}
__device__ __forceinline__ void cp16(uint32_t dst, const void* src) {
    asm volatile("cp.async.cg.shared.global [%0], [%1], 16;" :: "r"(dst), "l"(src) : "memory");
}
#define CP_COMMIT()  asm volatile("cp.async.commit_group;" ::: "memory")
#define CP_WAIT1()   asm volatile("cp.async.wait_group 1;" ::: "memory")
#define SW128(o) ((o) ^ (((o) >> 3) & 0x70))

__device__ __forceinline__ void ldsm_x4(uint32_t* r, uint32_t addr) {
    asm volatile("ldmatrix.sync.aligned.m8n8.x4.shared.b16 {%0,%1,%2,%3}, [%4];"
                 : "=r"(r[0]), "=r"(r[1]), "=r"(r[2]), "=r"(r[3]) : "r"(addr));
}
__device__ __forceinline__ void ldsm_x2(uint32_t* r, uint32_t addr) {
    asm volatile("ldmatrix.sync.aligned.m8n8.x2.shared.b16 {%0,%1}, [%2];"
                 : "=r"(r[0]), "=r"(r[1]) : "r"(addr));
}
__device__ __forceinline__ void mma16816(float* c, const uint32_t* a, const uint32_t* b) {
    asm volatile(
        "mma.sync.aligned.m16n8k16.row.col.f32.f16.f16.f32 "
        "{%0,%1,%2,%3}, {%4,%5,%6,%7}, {%8,%9}, {%0,%1,%2,%3};"
        : "+f"(c[0]), "+f"(c[1]), "+f"(c[2]), "+f"(c[3])
        : "r"(a[0]), "r"(a[1]), "r"(a[2]), "r"(a[3]), "r"(b[0]), "r"(b[1]));
}

// ---------------- conversion kernels -----------------------------------------
__global__ void gather_convert(const float* __restrict__ x, const int* __restrict__ nz,
                               __half* __restrict__ g) {
    size_t idx  = (size_t)blockIdx.x * blockDim.x + threadIdx.x;  // over MACT*EMBED/4
    int    row  = (int)(idx >> 10);            // EMBED/4 = 1024 float4 per row
    int    col4 = (int)(idx & 1023);
    int    blk  = row >> 7;
    int    srow = nz[blk] * BLOCK + (row & 127);
    float4 v = reinterpret_cast<const float4*>(x)[(size_t)srow * (EMBED / 4) + col4];
    __half2* dst = reinterpret_cast<__half2*>(g + (size_t)row * EMBED + (size_t)col4 * 4);
    dst[0] = __floats2half2_rn(v.x, v.y);
    dst[1] = __floats2half2_rn(v.z, v.w);
}

// in [R,C] fp32 row-major -> out [C,R] fp16 row-major
__global__ void transpose_convert(const float* __restrict__ in, __half* __restrict__ out,
                                  int R, int C) {
    __shared__ float tile[32][33];
    int c0 = blockIdx.x * 32, r0 = blockIdx.y * 32;
    int tx = threadIdx.x, ty = threadIdx.y;  // (32,8)
#pragma unroll
    for (int i = 0; i < 4; i++) {
        int y = ty + i * 8;
        tile[y][tx] = in[(size_t)(r0 + y) * C + c0 + tx];
    }
    __syncthreads();
#pragma unroll
    for (int i = 0; i < 4; i++) {
        int y = ty + i * 8;
        out[(size_t)(c0 + y) * R + r0 + tx] = __float2half(tile[tx][y]);
    }
}

// ---------------- HMMA GEMM ---------------------------------------------------
// LIMITER MODEL (R5-R10): smem crossbar (128B/cyc/SM) binds: 128KB LDSM reads +
// 32KB cp.async writes per 128x128x64 iter = ~2048 cyc vs ~973 tensor cyc -> 49%.
// FIX: CTA 128x256, warp tile 64x64 (8 warps, 2m x 4n): per-iter traffic per MAC
// halves (128KB reads + 48KB writes per 1024 MMAs) -> tensor bound ~71%.
// 4-stage cp.async (192KB smem), m-fast grid (L2-resident operands),
// proven fragment loaders (A: ldsm_x4, B: ldsm_x2 per n8-tile).
constexpr int BM = 128, BN = 256, BK = 64, STAGES = 4;
constexpr uint32_t ABYTES      = BM * BK * 2;           // 16384
constexpr uint32_t BBYTES      = BN * BK * 2;           // 32768
constexpr uint32_t STAGE_BYTES = ABYTES + BBYTES;       // 49152
constexpr uint32_t SMEM_DYN    = STAGES * STAGE_BYTES;  // 196608

// A fragments: 4 m16-tiles (rows wm*64 + i*16), one ldsm_x4 each (proven pattern)
__device__ __forceinline__ void load_frag_a(uint32_t (&a)[4][4], uint32_t sA,
                                            int wm, int lane, int ks) {
#pragma unroll
    for (int i = 0; i < 4; i++) {
        const uint32_t r  = (uint32_t)(wm * 64 + i * 16 + (lane & 15));
        const uint32_t cb = (uint32_t)(ks * 32 + ((lane >> 4) << 4));
        ldsm_x4(a[i], sA + SW128(r * 128 + cb));
    }
}
// B fragments: 8 n8-tiles (rows wn*64 + j*8), one ldsm_x2 each (proven pattern)
__device__ __forceinline__ void load_frag_b(uint32_t (&b)[8][2], uint32_t sB,
                                            int wn, int lane, int ks) {
#pragma unroll
    for (int j = 0; j < 8; j++) {
        const uint32_t r  = (uint32_t)(wn * 64 + j * 8 + (lane & 7));
        const uint32_t cb = (uint32_t)(ks * 32 + (((lane >> 3) & 1) << 4));
        ldsm_x2(b[j], sB + SW128(r * 128 + cb));
    }
}

template <int KTOT, int LDC, bool SCATTER>
__global__ void __launch_bounds__(256, 1)
gemm_f16(const __half* __restrict__ A, const __half* __restrict__ B,
         void* __restrict__ C, const int* __restrict__ nz) {
    extern __shared__ char smem[];
    const uint32_t sb = smem_u32(smem);
    const int tid  = threadIdx.x;
    const int lane = tid & 31, wid = tid >> 5;
    const int wm = wid >> 2, wn = wid & 3;             // 2m x 4n warps, 64x64 tiles
    const int m0 = blockIdx.x * BM, n0 = blockIdx.y * BN;   // m-fast grid
    constexpr int KIT = KTOT / BK;

    // cp.async: stage = 384 rows x 128B (rows 0-127 = A, 128-383 = B).
    // thread t owns fixed 16B-chunk (t&7) of rows (t>>3) + 32p, p = 0..11.
    // p 0-3 -> A rows, p 4-11 -> B rows (exact split since t>>3 < 32).
    const int rb = tid >> 3;                 // base row 0..31
    const int chb = (tid & 7) * 16;          // byte chunk within 128B row
    const char* gAt = (const char*)(A + (size_t)(m0 + rb) * KTOT) + chb;
    const char* gBt = (const char*)(B + (size_t)(n0 + rb) * KTOT) + chb;
    const size_t rstep = (size_t)32 * KTOT * 2;   // 32 rows in bytes

    float acc[4][8][4];
#pragma unroll
    for (int i = 0; i < 4; i++)
#pragma unroll
        for (int j = 0; j < 8; j++)
#pragma unroll
            for (int q = 0; q < 4; q++) acc[i][j][q] = 0.f;

    // prologue: fill stages 0..2 (3 commits)
#pragma unroll
    for (int s = 0; s < STAGES - 1; s++) {
        const uint32_t st = sb + (uint32_t)s * STAGE_BYTES;
        const size_t ko = (size_t)s * (BK * 2);
#pragma unroll
        for (int p = 0; p < 4; p++)
            cp16(st + SW128((uint32_t)((rb + 32 * p) * 128 + chb)),
                 gAt + ko + (size_t)p * rstep);
#pragma unroll
        for (int p = 0; p < 8; p++)
            cp16(st + ABYTES + SW128((uint32_t)((rb + 32 * p) * 128 + chb)),
                 gBt + ko + (size_t)p * rstep);
        CP_COMMIT();
    }

    uint32_t af[2][4][4], bf[2][8][2];   // double-buffered fragments

    for (int it = 0; it < KIT; it++) {
        // stages <= it+1 resident after this wait (3+it committed, <=1 pending)
        CP_WAIT1();
        __syncthreads();

        // issue stage it+3 into slot (it+3)&3 (disjoint from compute slot it&3)
        const int ls = it + STAGES - 1;
        if (ls < KIT) {
            const uint32_t st = sb + (uint32_t)(ls & (STAGES - 1)) * STAGE_BYTES;
            const size_t ko = (size_t)ls * (BK * 2);
#pragma unroll
            for (int p = 0; p < 4; p++)
                cp16(st + SW128((uint32_t)((rb + 32 * p) * 128 + chb)),
                     gAt + ko + (size_t)p * rstep);
#pragma unroll
            for (int p = 0; p < 8; p++)
                cp16(st + ABYTES + SW128((uint32_t)((rb + 32 * p) * 128 + chb)),
                     gBt + ko + (size_t)p * rstep);
        }
        CP_COMMIT();

        const uint32_t sA  = sb + (uint32_t)(it & (STAGES - 1)) * STAGE_BYTES;
        const uint32_t sBs = sA + ABYTES;

        if (it == 0) {             // prime buffer 0 (later iters arrive pre-loaded)
            load_frag_a(af[0], sA, wm, lane, 0);
            load_frag_b(bf[0], sBs, wn, lane, 0);
        }

#pragma unroll
        for (int ks = 0; ks < 4; ks++) {
            const int cur = ks & 1, nxt = cur ^ 1;
            if (ks < 3) {
                load_frag_a(af[nxt], sA, wm, lane, ks + 1);
                load_frag_b(bf[nxt], sBs, wn, lane, ks + 1);
            } else if (it + 1 < KIT) {
                // prefetch ks=0 of NEXT stage (resident per CP_WAIT1 above)
                const uint32_t nA = sb + (uint32_t)((it + 1) & (STAGES - 1)) * STAGE_BYTES;
                load_frag_a(af[nxt], nA, wm, lane, 0);
                load_frag_b(bf[nxt], nA + ABYTES, wn, lane, 0);
            }
#pragma unroll
            for (int i = 0; i < 4; i++)
#pragma unroll
                for (int j = 0; j < 8; j++)
                    mma16816(acc[i][j], af[cur][i], bf[cur][j]);
        }
    }

    // ---------------- epilogue ----------------
    // frag (i,j): rows wm*64+i*16+lane/4 (+8), cols wn*64+j*8+2*(lane%4)
    const int rbase = wm * 64 + (lane >> 2);
    const int cbase = n0 + wn * 64 + 2 * (lane & 3);
    if (!SCATTER) {
        __half* Ch = (__half*)C;
#pragma unroll
        for (int i = 0; i < 4; i++) {
#pragma unroll
            for (int j = 0; j < 8; j++) {
                const int col = cbase + j * 8;
                const size_t r0 = (size_t)(m0 + rbase + i * 16) * LDC + col;
                const size_t r1 = r0 + (size_t)8 * LDC;
                *reinterpret_cast<__half2*>(Ch + r0) =
                    __floats2half2_rn(acc[i][j][0], acc[i][j][1]);
                *reinterpret_cast<__half2*>(Ch + r1) =
                    __floats2half2_rn(acc[i][j][2], acc[i][j][3]);
            }
        }
    } else {
        float* Cf = (float*)C;
        const int orow = nz[blockIdx.x] * BLOCK;   // m-tile (blockIdx.x) == source block
#pragma unroll
        for (int i = 0; i < 4; i++) {
#pragma unroll
            for (int j = 0; j < 8; j++) {
                const int col = cbase + j * 8;
                const size_t r0 = (size_t)(orow + rbase + i * 16) * LDC + col;
                const size_t r1 = r0 + (size_t)8 * LDC;
                *reinterpret_cast<float2*>(Cf + r0) =
                    make_float2(acc[i][j][0], acc[i][j][1]);
                *reinterpret_cast<float2*>(Cf + r1) =
                    make_float2(acc[i][j][2], acc[i][j][3]);
            }
        }
    }
}

// ---------------- launch ------------------------------------------------------
extern "C" void kernel_launch(void* const* d_in, const int* in_sizes, int n_in,
                              void* d_out, int out_size) {
    const float* x   = (const float*)d_in[0];
    const float* fc1 = (const float*)d_in[1];
    const float* fc2 = (const float*)d_in[2];
    const int*   nz  = (const int*)d_in[3];
    (void)in_sizes; (void)n_in;

    void *pg, *pw1, *pw2, *ph;
    cudaGetSymbolAddress(&pg,  d_g);
    cudaGetSymbolAddress(&pw1, d_w1t);
    cudaGetSymbolAddress(&pw2, d_w2t);
    cudaGetSymbolAddress(&ph,  d_h);

    cudaFuncSetAttribute(gemm_f16<EMBED, HIDDEN, false>,
                         cudaFuncAttributeMaxDynamicSharedMemorySize, SMEM_DYN);
    cudaFuncSetAttribute(gemm_f16<HIDDEN, OUTD, true>,
                         cudaFuncAttributeMaxDynamicSharedMemorySize, SMEM_DYN);

    // zero full output (non-active blocks must be 0)
    cudaMemsetAsync(d_out, 0, (size_t)out_size * sizeof(float));

    // fp16 conversions
    gather_convert<<<(MACT * (EMBED / 4)) / 256, 256>>>(x, nz, (__half*)pg);
    transpose_convert<<<dim3(HIDDEN / 32, EMBED / 32), dim3(32, 8)>>>(fc1, (__half*)pw1, EMBED, HIDDEN);
    transpose_convert<<<dim3(OUTD / 32, HIDDEN / 32), dim3(32, 8)>>>(fc2, (__half*)pw2, HIDDEN, OUTD);

    // GEMM1: h = g @ fc1^T-layout   (M=4096, N=16384, K=4096), m-fast grid
    gemm_f16<EMBED, HIDDEN, false>
        <<<dim3(MACT / BM, HIDDEN / BN), 256, SMEM_DYN>>>(
            (const __half*)pg, (const __half*)pw1, ph, nz);

    // GEMM2: out[nz] = h @ fc2^T-layout   (M=4096, N=4096, K=16384), fp32 scatter
    gemm_f16<HIDDEN, OUTD, true>
        <<<dim3(MACT / BM, OUTD / BN), 256, SMEM_DYN>>>(
            (const __half*)ph, (const __half*)pw2, d_out, nz);
}